// round 6
// baseline (speedup 1.0000x reference)
#include <cuda_runtime.h>
#include <cstddef>

#define NCOL 2048
#define NROW 16384
#define THREADS 128
#define WPB 4                    // warps per block
#define RPW 14                   // rows per warp (lanes 14..31 pad/clamp)
#define RPB (WPB * RPW)          // 56 rows per block
#define W 64                     // tile width (columns)
#define NT (NCOL / W)            // 32 tiles
#define LDW 68                   // padded smem row stride in floats (272B)
#define TILE_F (RPW * LDW)       // 952 floats per tile buffer
#define NIN 4                    // input ring depth (per warp)
#define WBUF_F ((NIN + 2) * TILE_F)   // per-warp buffer floats (5712)
#define SMEM_FLOATS (2 * NCOL + WPB * WBUF_F)
#define SMEM_BYTES (SMEM_FLOATS * 4)  // 16KB cs + 4*22.8KB ~= 107.4KB -> 2 CTAs/SM
#define CHUNKS_PER_LANE ((RPW * (W / 4)) / 32)   // 224/32 = 7

__device__ __forceinline__ void cp_async16(float* smem_dst, const float* gsrc) {
    unsigned s = (unsigned)__cvta_generic_to_shared(smem_dst);
    asm volatile("cp.async.cg.shared.global [%0], [%1], 16;" :: "r"(s), "l"(gsrc));
}
__device__ __forceinline__ void cp_commit() { asm volatile("cp.async.commit_group;"); }

__global__ void __launch_bounds__(THREADS, 2)
ring_givens_kernel(const float* __restrict__ x,
                   const float* __restrict__ angles,
                   float* __restrict__ out) {
    extern __shared__ float smem[];
    float2* cs = (float2*)smem;                       // [2048] (cos, sin)
    const int tid  = threadIdx.x;
    const int wid  = tid >> 5;
    const int lane = tid & 31;

    float* inb = smem + 2 * NCOL + wid * WBUF_F;      // NIN input tiles
    float* otb = inb + NIN * TILE_F;                  // 2 output staging tiles

    const long long wgid = (long long)blockIdx.x * WPB + wid;
    const long long base = wgid * RPW;                // first row of this warp
    const bool active = (base < NROW);

    // --- prefetch first NIN tiles (highest column tiles first), warp-private ---
    if (active) {
        #pragma unroll
        for (int p = 0; p < NIN; ++p) {
            int it = NT - 1 - p;
            float* buf = inb + (it & (NIN - 1)) * TILE_F;
            #pragma unroll
            for (int j = 0; j < CHUNKS_PER_LANE; ++j) {
                int q  = lane + j * 32;
                int r  = q >> 4;                       // local row 0..13
                int c4 = (q & 15) << 2;
                long long grow = base + r;
                if (grow >= NROW) grow = NROW - 1;     // clamp (tail warps)
                cp_async16(buf + r * LDW + c4,
                           x + grow * NCOL + it * W + c4);
            }
            cp_commit();
        }
    }

    // --- cos/sin table (block-cooperative, overlaps the prefetches) ---
    for (int k = tid; k < NCOL; k += THREADS) {
        float sv, cv;
        sincosf(angles[k], &sv, &cv);
        cs[k] = make_float2(cv, sv);
    }
    __syncthreads();          // only block barrier in the kernel
    if (!active) return;

    const int cl = (lane < RPW) ? lane : (RPW - 1);   // clamped compute lane
    const bool wr = (lane < RPW);
    long long rowc = base + cl;
    if (rowc >= NROW) rowc = NROW - 1;
    const float x0 = x[rowc * NCOL];                  // wrap partner of col 2047

    const float4* csf4 = (const float4*)cs;  // {c(2m), s(2m), c(2m+1), s(2m+1)}

    float t = 0.f, v0run = 0.f;
    float c0r = 0.f, c1r = 0.f, c2r = 0.f;            // carried outputs

    for (int i = NT - 1; i >= 0; --i) {
        asm volatile("cp.async.wait_group %0;" :: "n"(NIN - 1));
        __syncwarp();      // tile i visible warp-wide; prev store loop drained

        const float* bin = inb + (i & (NIN - 1)) * TILE_F + cl * LDW;
        float* otc = otb + (i & 1) * TILE_F + cl * LDW;        // cols [k0, k0+W)
        float* otn = otb + ((i + 1) & 1) * TILE_F + cl * LDW;  // cols [k0+W, ..)
        const int k0 = i * W;

        #pragma unroll
        for (int q = 15; q >= 0; --q) {
            float4 u4 = *(const float4*)(bin + 4 * q);
            float4 cB = csf4[(k0 >> 1) + 2 * q];      // k0+4q, k0+4q+1
            float4 cA = csf4[(k0 >> 1) + 2 * q + 1];  // k0+4q+2, k0+4q+3

            if (i == NT - 1 && q == 15) {
                // wrap rotation k = 2047: plane (2047, 0). No output yet.
                t     = cA.z * u4.w - cA.w * x0;
                v0run = cA.w * u4.w + cA.z * x0;
            } else {
                // step k = k0+4q+3 -> out[k0+4q+4]
                float O3 = cA.w * u4.w + cA.z * t;
                t        = cA.z * u4.w - cA.w * t;
                float4 st4 = make_float4(O3, c0r, c1r, c2r);
                if (wr) {
                    if (q == 15) *(float4*)otn = st4;                // slots 0..3
                    else         *(float4*)(otc + 4 * q + 4) = st4;  // 4q+4..4q+7
                }
            }
            float O2 = cA.y * u4.z + cA.x * t;   // k0+4q+2 -> slot 4q+3
            t        = cA.x * u4.z - cA.y * t;
            float O1 = cB.w * u4.y + cB.z * t;   // k0+4q+1 -> slot 4q+2
            t        = cB.z * u4.y - cB.w * t;
            float u0 = (i == 0 && q == 0) ? v0run : u4.x;
            float O0 = cB.y * u0 + cB.x * t;     // k0+4q   -> slot 4q+1
            t        = cB.x * u0 - cB.y * t;
            c0r = O0; c1r = O1; c2r = O2;
        }

        __syncwarp();      // all lanes done reading inbuf slot + staging writes

        // prefetch tile i-NIN into the just-freed slot (slot (i-NIN)&3 == i&3);
        // always commit so wait_group accounting stays uniform in the tail
        if (i >= NIN) {
            int ip = i - NIN;
            float* buf = inb + (i & (NIN - 1)) * TILE_F;
            #pragma unroll
            for (int j = 0; j < CHUNKS_PER_LANE; ++j) {
                int q  = lane + j * 32;
                int r  = q >> 4;
                int c4 = (q & 15) << 2;
                long long grow = base + r;
                if (grow >= NROW) grow = NROW - 1;
                cp_async16(buf + r * LDW + c4,
                           x + grow * NCOL + ip * W + c4);
            }
        }
        cp_commit();

        // store the now-complete buffer: out columns [(i+1)*W, (i+2)*W)
        if (i < NT - 1) {
            const float* sb = otb + ((i + 1) & 1) * TILE_F;
            const int col0 = (i + 1) * W;
            #pragma unroll
            for (int j = 0; j < CHUNKS_PER_LANE; ++j) {
                int q  = lane + j * 32;
                int r  = q >> 4;
                int c4 = (q & 15) << 2;
                long long grow = base + r;
                if (grow < NROW)
                    *(float4*)(out + grow * NCOL + col0 + c4) =
                        *(const float4*)(sb + r * LDW + c4);
            }
        }
    }

    // finalize buffer parity 0 (out columns [0, W)): slot0 = {out[0]=t, carries}
    if (wr) *(float4*)(otb + cl * LDW) = make_float4(t, c0r, c1r, c2r);
    __syncwarp();
    {
        const float* sb = otb;
        #pragma unroll
        for (int j = 0; j < CHUNKS_PER_LANE; ++j) {
            int q  = lane + j * 32;
            int r  = q >> 4;
            int c4 = (q & 15) << 2;
            long long grow = base + r;
            if (grow < NROW)
                *(float4*)(out + grow * NCOL + c4) =
                    *(const float4*)(sb + r * LDW + c4);
        }
    }
}

extern "C" void kernel_launch(void* const* d_in, const int* in_sizes, int n_in,
                              void* d_out, int out_size) {
    const float* x      = (const float*)d_in[0];
    const float* angles = (const float*)d_in[1];
    if (n_in >= 2 && in_sizes[0] < in_sizes[1]) {   // defensive ordering
        x      = (const float*)d_in[1];
        angles = (const float*)d_in[0];
    }
    float* out = (float*)d_out;

    cudaFuncSetAttribute(ring_givens_kernel,
                         cudaFuncAttributeMaxDynamicSharedMemorySize, SMEM_BYTES);
    int grid = (NROW + RPB - 1) / RPB;   // 293
    ring_givens_kernel<<<grid, THREADS, SMEM_BYTES>>>(x, angles, out);
}

// round 7
// speedup vs baseline: 1.0011x; 1.0011x over previous
#include <cuda_runtime.h>
#include <cstddef>

#define NCOL 2048
#define NROW 16384
#define THREADS 128
#define WPB 4                    // warps per block
#define RPW 14                   // rows per warp (lanes 14..31 pad/clamp)
#define RPB (WPB * RPW)          // 56 rows per block
#define W 64                     // tile width (columns)
#define NT (NCOL / W)            // 32 tiles
#define LDW 68                   // padded smem row stride in floats (272B)
#define TILE_F (RPW * LDW)       // 952 floats per tile buffer
#define NIN 3                    // input ring depth (per warp), mod-3
#define NOUT 3                   // output staging depth, mod-3
#define WBUF_F ((NIN + NOUT) * TILE_F)
#define SMEM_FLOATS (2 * NCOL + WPB * WBUF_F)
#define SMEM_BYTES (SMEM_FLOATS * 4)  // 16KB cs + 4*22.8KB ~= 107.4KB -> 2 CTAs/SM
#define CHUNKS_PER_LANE ((RPW * (W / 4)) / 32)   // 224/32 = 7

__device__ __forceinline__ void cp_async16(float* smem_dst, const float* gsrc) {
    unsigned s = (unsigned)__cvta_generic_to_shared(smem_dst);
    asm volatile("cp.async.cg.shared.global [%0], [%1], 16;" :: "r"(s), "l"(gsrc));
}
__device__ __forceinline__ void cp_commit() { asm volatile("cp.async.commit_group;"); }

__device__ __forceinline__ void bulk_store_row(float* gdst, const float* ssrc, unsigned bytes) {
    unsigned s = (unsigned)__cvta_generic_to_shared(ssrc);
    asm volatile("cp.async.bulk.global.shared::cta.bulk_group [%0], [%1], %2;"
                 :: "l"(gdst), "r"(s), "r"(bytes) : "memory");
}
__device__ __forceinline__ void bulk_commit() {
    asm volatile("cp.async.bulk.commit_group;" ::: "memory");
}

__global__ void __launch_bounds__(THREADS, 2)
ring_givens_kernel(const float* __restrict__ x,
                   const float* __restrict__ angles,
                   float* __restrict__ out) {
    extern __shared__ float smem[];
    float2* cs = (float2*)smem;                       // [2048] (cos, sin)
    const int tid  = threadIdx.x;
    const int wid  = tid >> 5;
    const int lane = tid & 31;

    float* inb = smem + 2 * NCOL + wid * WBUF_F;      // NIN input tiles
    float* otb = inb + NIN * TILE_F;                  // NOUT output staging tiles

    const long long wgid = (long long)blockIdx.x * WPB + wid;
    const long long base = wgid * RPW;                // first row of this warp
    const bool active = (base < NROW);

    // --- prefetch first NIN tiles (highest column tiles first), warp-private ---
    if (active) {
        #pragma unroll
        for (int p = 0; p < NIN; ++p) {
            int it = NT - 1 - p;
            float* buf = inb + (it % 3) * TILE_F;
            #pragma unroll
            for (int j = 0; j < CHUNKS_PER_LANE; ++j) {
                int q  = lane + j * 32;
                int r  = q >> 4;                       // local row 0..13
                int c4 = (q & 15) << 2;
                long long grow = base + r;
                if (grow >= NROW) grow = NROW - 1;     // clamp (tail warps)
                cp_async16(buf + r * LDW + c4,
                           x + grow * NCOL + it * W + c4);
            }
            cp_commit();
        }
    }

    // --- cos/sin table (block-cooperative, overlaps the prefetches) ---
    for (int k = tid; k < NCOL; k += THREADS) {
        float sv, cv;
        sincosf(angles[k], &sv, &cv);
        cs[k] = make_float2(cv, sv);
    }
    __syncthreads();          // only block barrier in the kernel
    if (!active) return;

    const int cl = (lane < RPW) ? lane : (RPW - 1);   // clamped compute lane
    const bool wr = (lane < RPW);
    const bool rowok = wr && (base + lane < NROW);    // this lane owns a real row
    float* gout_row = out + (base + (rowok ? lane : 0)) * NCOL;  // lane's out row

    long long rowc = base + cl;
    if (rowc >= NROW) rowc = NROW - 1;
    const float x0 = x[rowc * NCOL];                  // wrap partner of col 2047

    const float4* csf4 = (const float4*)cs;  // {c(2m), s(2m), c(2m+1), s(2m+1)}

    float t = 0.f, v0run = 0.f;
    float c0r = 0.f, c1r = 0.f, c2r = 0.f;            // carried outputs

    for (int i = NT - 1; i >= 0; --i) {
        asm volatile("cp.async.wait_group %0;" :: "n"(NIN - 1));  // tile i landed
        // staging buffers touched this iter: otc=OB[i%3] (bulk from iter i+2),
        // otn=OB[(i+1)%3] (bulk from iter i+3). wait.read 1 leaves only iter
        // i+1's group outstanding -> both safe to overwrite.
        asm volatile("cp.async.bulk.wait_group.read 1;" ::: "memory");
        __syncwarp();

        const float* bin = inb + (i % 3) * TILE_F + cl * LDW;
        float* otc = otb + (i % 3) * TILE_F + cl * LDW;        // cols [k0, k0+W)
        float* otn = otb + ((i + 1) % 3) * TILE_F + cl * LDW;  // cols [k0+W, ..)
        const int k0 = i * W;

        #pragma unroll
        for (int q = 15; q >= 0; --q) {
            float4 u4 = *(const float4*)(bin + 4 * q);
            float4 cB = csf4[(k0 >> 1) + 2 * q];      // k0+4q, k0+4q+1
            float4 cA = csf4[(k0 >> 1) + 2 * q + 1];  // k0+4q+2, k0+4q+3

            if (i == NT - 1 && q == 15) {
                // wrap rotation k = 2047: plane (2047, 0). No output yet.
                t     = cA.z * u4.w - cA.w * x0;
                v0run = cA.w * u4.w + cA.z * x0;
            } else {
                // step k = k0+4q+3 -> out[k0+4q+4]
                float O3 = cA.w * u4.w + cA.z * t;
                t        = cA.z * u4.w - cA.w * t;
                float4 st4 = make_float4(O3, c0r, c1r, c2r);
                if (wr) {
                    if (q == 15) *(float4*)otn = st4;                // slots 0..3
                    else         *(float4*)(otc + 4 * q + 4) = st4;  // 4q+4..4q+7
                }
            }
            float O2 = cA.y * u4.z + cA.x * t;   // k0+4q+2 -> slot 4q+3
            t        = cA.x * u4.z - cA.y * t;
            float O1 = cB.w * u4.y + cB.z * t;   // k0+4q+1 -> slot 4q+2
            t        = cB.z * u4.y - cB.w * t;
            float u0 = (i == 0 && q == 0) ? v0run : u4.x;
            float O0 = cB.y * u0 + cB.x * t;     // k0+4q   -> slot 4q+1
            t        = cB.x * u0 - cB.y * t;
            c0r = O0; c1r = O1; c2r = O2;
        }

        __syncwarp();      // all lanes done reading inbuf slot + staging writes

        // prefetch tile i-NIN into the just-freed input slot (slot i%3);
        // always commit so LDGSTS wait_group accounting stays uniform
        if (i >= NIN) {
            int ip = i - NIN;
            float* buf = inb + (i % 3) * TILE_F;
            #pragma unroll
            for (int j = 0; j < CHUNKS_PER_LANE; ++j) {
                int q  = lane + j * 32;
                int r  = q >> 4;
                int c4 = (q & 15) << 2;
                long long grow = base + r;
                if (grow >= NROW) grow = NROW - 1;
                cp_async16(buf + r * LDW + c4,
                           x + grow * NCOL + ip * W + c4);
            }
        }
        cp_commit();

        // async bulk-store the now-complete buffer OB[(i+1)%3]:
        // out columns [(i+1)*W, (i+2)*W), one 256B bulk per row, lane-parallel
        asm volatile("fence.proxy.async.shared::cta;" ::: "memory");
        if (i < NT - 1) {
            const float* sb = otb + ((i + 1) % 3) * TILE_F;
            if (rowok)
                bulk_store_row(gout_row + (i + 1) * W, sb + lane * LDW, W * 4);
        }
        bulk_commit();     // one bulk group per iteration (empty at i=NT-1)
    }

    // finalize OB[0] (out columns [0, W)): slot0 = {out[0]=t, carries}
    if (wr) *(float4*)(otb + cl * LDW) = make_float4(t, c0r, c1r, c2r);
    __syncwarp();
    asm volatile("fence.proxy.async.shared::cta;" ::: "memory");
    if (rowok)
        bulk_store_row(gout_row, otb + lane * LDW, W * 4);
    bulk_commit();
    asm volatile("cp.async.bulk.wait_group 0;" ::: "memory");  // writes visible
}

extern "C" void kernel_launch(void* const* d_in, const int* in_sizes, int n_in,
                              void* d_out, int out_size) {
    const float* x      = (const float*)d_in[0];
    const float* angles = (const float*)d_in[1];
    if (n_in >= 2 && in_sizes[0] < in_sizes[1]) {   // defensive ordering
        x      = (const float*)d_in[1];
        angles = (const float*)d_in[0];
    }
    float* out = (float*)d_out;

    cudaFuncSetAttribute(ring_givens_kernel,
                         cudaFuncAttributeMaxDynamicSharedMemorySize, SMEM_BYTES);
    int grid = (NROW + RPB - 1) / RPB;   // 293
    ring_givens_kernel<<<grid, THREADS, SMEM_BYTES>>>(x, angles, out);
}

// round 8
// speedup vs baseline: 1.0028x; 1.0017x over previous
#include <cuda_runtime.h>
#include <cstddef>

#define NCOL 2048
#define NROW 16384
#define THREADS 128
#define WPB 4                    // warps per block
#define RPW 14                   // rows per warp (lanes 14..31 idle in compute)
#define RPB (WPB * RPW)          // 56 rows per block
#define W 64                     // tile width (columns)
#define NT (NCOL / W)            // 32 tiles
#define LDW 68                   // padded smem row stride in floats (272B)
#define TILE_F (RPW * LDW)       // 952 floats per tile buffer
#define NIN 4                    // input ring depth (per warp)
#define WBUF_F ((NIN + 2) * TILE_F)   // per-warp buffer floats (5712)
#define SMEM_FLOATS (2 * NCOL + WPB * WBUF_F)
#define SMEM_BYTES (SMEM_FLOATS * 4)  // 16KB cs + 4*22.8KB ~= 107.4KB -> 2 CTAs/SM
#define CHUNKS_PER_LANE ((RPW * (W / 4)) / 32)   // 224/32 = 7

__device__ __forceinline__ void cp_async16(float* smem_dst, const float* gsrc) {
    unsigned s = (unsigned)__cvta_generic_to_shared(smem_dst);
    asm volatile("cp.async.cg.shared.global [%0], [%1], 16;" :: "r"(s), "l"(gsrc));
}
__device__ __forceinline__ void cp_commit() { asm volatile("cp.async.commit_group;"); }

__global__ void __launch_bounds__(THREADS, 2)
ring_givens_kernel(const float* __restrict__ x,
                   const float* __restrict__ angles,
                   float* __restrict__ out) {
    extern __shared__ float smem[];
    float2* cs = (float2*)smem;                       // [2048] (cos, sin)
    const int tid  = threadIdx.x;
    const int wid  = tid >> 5;
    const int lane = tid & 31;

    float* inb = smem + 2 * NCOL + wid * WBUF_F;      // NIN input tiles
    float* otb = inb + NIN * TILE_F;                  // 2 output staging tiles

    const long long wgid = (long long)blockIdx.x * WPB + wid;
    const long long base = wgid * RPW;                // first row of this warp
    const bool active = (base < NROW);

    // --- prefetch first NIN tiles (highest column tiles first), warp-private ---
    if (active) {
        #pragma unroll
        for (int p = 0; p < NIN; ++p) {
            int it = NT - 1 - p;
            float* buf = inb + (it & (NIN - 1)) * TILE_F;
            #pragma unroll
            for (int j = 0; j < CHUNKS_PER_LANE; ++j) {
                int q  = lane + j * 32;
                int r  = q >> 4;                       // local row 0..13
                int c4 = (q & 15) << 2;
                long long grow = base + r;
                if (grow >= NROW) grow = NROW - 1;     // clamp (tail warps)
                cp_async16(buf + r * LDW + c4,
                           x + grow * NCOL + it * W + c4);
            }
            cp_commit();
        }
    }

    // --- cos/sin table (block-cooperative, overlaps the prefetches) ---
    for (int k = tid; k < NCOL; k += THREADS) {
        float sv, cv;
        sincosf(angles[k], &sv, &cv);
        cs[k] = make_float2(cv, sv);
    }
    __syncthreads();          // only block barrier in the kernel
    if (!active) return;

    const bool wr = (lane < RPW) && (base + lane < NROW);  // lane owns a row
    const int  cl = wr ? lane : 0;                         // compute lane row
    const float x0 = wr ? x[(base + cl) * NCOL] : 0.f;     // wrap partner of col 2047

    const float4* csf4 = (const float4*)cs;  // {c(2m), s(2m), c(2m+1), s(2m+1)}

    float t = 0.f, v0run = 0.f;
    float c0r = 0.f, c1r = 0.f, c2r = 0.f;            // carried outputs

    for (int i = NT - 1; i >= 0; --i) {
        asm volatile("cp.async.wait_group %0;" :: "n"(NIN - 1));
        __syncwarp();      // tile i visible warp-wide; prev store loop drained

        const int k0 = i * W;

        if (wr) {
            const float* bin = inb + (i & (NIN - 1)) * TILE_F + cl * LDW;
            float* otc = otb + (i & 1) * TILE_F + cl * LDW;        // [k0, k0+W)
            float* otn = otb + ((i + 1) & 1) * TILE_F + cl * LDW;  // [k0+W, ..)

            #pragma unroll
            for (int q = 15; q >= 0; --q) {
                float4 u4 = *(const float4*)(bin + 4 * q);
                float4 cB = csf4[(k0 >> 1) + 2 * q];      // k0+4q, k0+4q+1
                float4 cA = csf4[(k0 >> 1) + 2 * q + 1];  // k0+4q+2, k0+4q+3

                if (i == NT - 1 && q == 15) {
                    // wrap rotation k = 2047: plane (2047, 0). No output yet.
                    t     = cA.z * u4.w - cA.w * x0;
                    v0run = cA.w * u4.w + cA.z * x0;
                } else {
                    // step k = k0+4q+3 -> out[k0+4q+4]; 4-cyc t-chain form
                    float su3 = cA.w * u4.w, cu3 = cA.z * u4.w;
                    float O3  = fmaf(cA.z, t, su3);
                    t         = fmaf(-cA.w, t, cu3);
                    float4 st4 = make_float4(O3, c0r, c1r, c2r);
                    if (q == 15) *(float4*)otn = st4;                // slots 0..3
                    else         *(float4*)(otc + 4 * q + 4) = st4;  // 4q+4..4q+7
                }
                float su2 = cA.y * u4.z, cu2 = cA.x * u4.z;  // k0+4q+2 -> 4q+3
                float O2  = fmaf(cA.x, t, su2);
                t         = fmaf(-cA.y, t, cu2);
                float su1 = cB.w * u4.y, cu1 = cB.z * u4.y;  // k0+4q+1 -> 4q+2
                float O1  = fmaf(cB.z, t, su1);
                t         = fmaf(-cB.w, t, cu1);
                float u0  = (i == 0 && q == 0) ? v0run : u4.x;
                float su0 = cB.y * u0, cu0 = cB.x * u0;      // k0+4q   -> 4q+1
                float O0  = fmaf(cB.x, t, su0);
                t         = fmaf(-cB.y, t, cu0);
                c0r = O0; c1r = O1; c2r = O2;
            }
        }

        __syncwarp();      // all lanes done reading inbuf slot + staging writes

        // prefetch tile i-NIN into the just-freed slot (slot (i-NIN)&3 == i&3);
        // always commit so wait_group accounting stays uniform in the tail
        if (i >= NIN) {
            int ip = i - NIN;
            float* buf = inb + (i & (NIN - 1)) * TILE_F;
            #pragma unroll
            for (int j = 0; j < CHUNKS_PER_LANE; ++j) {
                int q  = lane + j * 32;
                int r  = q >> 4;
                int c4 = (q & 15) << 2;
                long long grow = base + r;
                if (grow >= NROW) grow = NROW - 1;
                cp_async16(buf + r * LDW + c4,
                           x + grow * NCOL + ip * W + c4);
            }
        }
        cp_commit();

        // store the now-complete buffer: out columns [(i+1)*W, (i+2)*W)
        if (i < NT - 1) {
            const float* sb = otb + ((i + 1) & 1) * TILE_F;
            const int col0 = (i + 1) * W;
            #pragma unroll
            for (int j = 0; j < CHUNKS_PER_LANE; ++j) {
                int q  = lane + j * 32;
                int r  = q >> 4;
                int c4 = (q & 15) << 2;
                long long grow = base + r;
                if (grow < NROW)
                    *(float4*)(out + grow * NCOL + col0 + c4) =
                        *(const float4*)(sb + r * LDW + c4);
            }
        }
    }

    // finalize buffer parity 0 (out columns [0, W)): slot0 = {out[0]=t, carries}
    if (wr) *(float4*)(otb + cl * LDW) = make_float4(t, c0r, c1r, c2r);
    __syncwarp();
    {
        const float* sb = otb;
        #pragma unroll
        for (int j = 0; j < CHUNKS_PER_LANE; ++j) {
            int q  = lane + j * 32;
            int r  = q >> 4;
            int c4 = (q & 15) << 2;
            long long grow = base + r;
            if (grow < NROW)
                *(float4*)(out + grow * NCOL + c4) =
                    *(const float4*)(sb + r * LDW + c4);
        }
    }
}

extern "C" void kernel_launch(void* const* d_in, const int* in_sizes, int n_in,
                              void* d_out, int out_size) {
    const float* x      = (const float*)d_in[0];
    const float* angles = (const float*)d_in[1];
    if (n_in >= 2 && in_sizes[0] < in_sizes[1]) {   // defensive ordering
        x      = (const float*)d_in[1];
        angles = (const float*)d_in[0];
    }
    float* out = (float*)d_out;

    cudaFuncSetAttribute(ring_givens_kernel,
                         cudaFuncAttributeMaxDynamicSharedMemorySize, SMEM_BYTES);
    int grid = (NROW + RPB - 1) / RPB;   // 293
    ring_givens_kernel<<<grid, THREADS, SMEM_BYTES>>>(x, angles, out);
}